// round 15
// baseline (speedup 1.0000x reference)
#include <cuda_runtime.h>
#include <cuda_fp16.h>
#include <cstdint>

// Problem constants: B=8, N=1024, C=768, H=12, HD=64
#define BATCH 8
#define SEQ   1024
#define CDIM  768
#define HEADS 12
#define HDIM  64
#define SCALE 0.125f
#define SM_LOG2E 1.4426950408889634f

// ---------------------------------------------------------------------------
// Persistent fp16 scratch (no cudaMalloc anywhere)
// ---------------------------------------------------------------------------
__device__ __half g_x [BATCH*SEQ*CDIM];
__device__ __half g_wq[3*CDIM*CDIM];
__device__ __half g_wp[CDIM*CDIM];
__device__ __half g_q [BATCH*HEADS*SEQ*HDIM];   // pre-scaled by SCALE*log2(e)
__device__ __half g_k [BATCH*HEADS*SEQ*HDIM];
__device__ __half g_v [BATCH*HEADS*SEQ*HDIM];
__device__ __half g_a [BATCH*SEQ*CDIM];

// ---------------------------------------------------------------------------
// helpers
// ---------------------------------------------------------------------------
__device__ __forceinline__ uint32_t smem_u32(const void* p) {
    uint32_t a;
    asm("{ .reg .u64 t; cvta.to.shared.u64 t, %1; cvt.u32.u64 %0, t; }" : "=r"(a) : "l"(p));
    return a;
}
__device__ __forceinline__ void cpa16(uint32_t dst, const void* src) {
    asm volatile("cp.async.cg.shared.global [%0], [%1], 16;"
                 :: "r"(dst), "l"(__cvta_generic_to_global(src)) : "memory");
}
#define CP_COMMIT() asm volatile("cp.async.commit_group;" ::: "memory")
#define CP_WAIT(n)  asm volatile("cp.async.wait_group %0;" :: "n"(n) : "memory")

__device__ __forceinline__ void ldsm4(uint32_t* r, uint32_t a) {
    asm volatile("ldmatrix.sync.aligned.m8n8.x4.shared.b16 {%0,%1,%2,%3}, [%4];"
                 : "=r"(r[0]), "=r"(r[1]), "=r"(r[2]), "=r"(r[3]) : "r"(a));
}
__device__ __forceinline__ void ldsm4t(uint32_t* r, uint32_t a) {
    asm volatile("ldmatrix.sync.aligned.m8n8.x4.trans.shared.b16 {%0,%1,%2,%3}, [%4];"
                 : "=r"(r[0]), "=r"(r[1]), "=r"(r[2]), "=r"(r[3]) : "r"(a));
}
__device__ __forceinline__ void mma16816(float* d, const uint32_t* a, uint32_t b0, uint32_t b1) {
    asm volatile("mma.sync.aligned.m16n8k16.row.col.f32.f16.f16.f32 "
                 "{%0,%1,%2,%3}, {%4,%5,%6,%7}, {%8,%9}, {%0,%1,%2,%3};"
                 : "+f"(d[0]), "+f"(d[1]), "+f"(d[2]), "+f"(d[3])
                 : "r"(a[0]), "r"(a[1]), "r"(a[2]), "r"(a[3]), "r"(b0), "r"(b1));
}
__device__ __forceinline__ uint32_t rnd2h(float a, float b) {
    __half2 h = __floats2half2_rn(a, b);
    return *(uint32_t*)&h;
}

// ---------------------------------------------------------------------------
// Fused conversion kernel: all three fp32 -> fp16 conversions in one launch
// ---------------------------------------------------------------------------
#define NX4  (BATCH*SEQ*CDIM/4)     // 1572864
#define NWQ4 (3*CDIM*CDIM/4)        // 442368
#define NWP4 (CDIM*CDIM/4)          // 147456

__global__ __launch_bounds__(256) void round_all_kernel(
        const float4* __restrict__ x, const float4* __restrict__ wq,
        const float4* __restrict__ wp,
        uint64_t* __restrict__ dx, uint64_t* __restrict__ dwq,
        uint64_t* __restrict__ dwp) {
    int i = blockIdx.x*blockDim.x + threadIdx.x;
    const float4* src; uint64_t* dst; int j;
    if (i < NX4)                 { src = x;  dst = dx;  j = i; }
    else if (i < NX4 + NWQ4)     { src = wq; dst = dwq; j = i - NX4; }
    else if (i < NX4+NWQ4+NWP4)  { src = wp; dst = dwp; j = i - NX4 - NWQ4; }
    else return;
    float4 v = src[j];
    dst[j] = ((uint64_t)rnd2h(v.z, v.w) << 32) | rnd2h(v.x, v.y);
}

// ---------------------------------------------------------------------------
// GEMM core: D[128xNB] = A16[128x768] * B16[NBx768]^T, BK=64, STAGES-deep
// cp.async ring, ONE __syncthreads per chunk. Single-product fp16.
// ---------------------------------------------------------------------------
#define GSTR 72
#define ATB  (128*GSTR*2)   // 18432 B per 128-row tile

template<int NB>
__device__ __forceinline__ void stage_gemm(uint32_t sbuf,
        const __half* A_g, const __half* B_g, int c) {
    const int tid = threadIdx.x;
    #pragma unroll
    for (int rep = 0; rep < 4; rep++) {
        int idx = tid + rep*256;
        int row = idx >> 3, cp = idx & 7;
        size_t so = (size_t)row*CDIM + c*64 + cp*8;
        cpa16(sbuf + row*(GSTR*2) + cp*16, A_g + so);
    }
    #pragma unroll
    for (int rep = 0; rep < NB/32; rep++) {
        int idx = tid + rep*256;
        int row = idx >> 3, cp = idx & 7;
        size_t so = (size_t)row*CDIM + c*64 + cp*8;
        cpa16(sbuf + ATB + row*(GSTR*2) + cp*16, B_g + so);
    }
}

template<int NB, int STAGES>
__device__ __forceinline__ void gemm_core(const __half* A_g, const __half* B_g,
                                          uint32_t sb, float acc[2][NB/16][4]) {
    constexpr int JP  = NB/32;
    constexpr int BTB = NB * GSTR * 2;
    constexpr int GSTAGE = ATB + BTB;
    const int tid = threadIdx.x;
    const int wid = tid >> 5, lane = tid & 31;
    const int wm = wid >> 1, wn = wid & 1;
    const int arow  = wm*32 + (lane & 15);
    const int acolb = (lane >> 4) << 3;
    const int brow  = wn*(NB/2) + ((lane >> 4) << 3) + (lane & 7);
    const int bcolb = ((lane >> 3) & 1) << 3;

    #pragma unroll
    for (int p = 0; p < STAGES - 1; p++) {
        stage_gemm<NB>(sb + p*GSTAGE, A_g, B_g, p);
        CP_COMMIT();
    }

    int slot = 0;
    for (int c = 0; c < 12; c++) {
        if (c + STAGES - 1 < 12) { CP_WAIT(STAGES - 2); } else { CP_WAIT(0); }
        __syncthreads();
        const int pre = c + STAGES - 1;
        if (pre < 12) {
            int ws = slot + STAGES - 1; if (ws >= STAGES) ws -= STAGES;
            stage_gemm<NB>(sb + ws*GSTAGE, A_g, B_g, pre);
            CP_COMMIT();
        }

        const uint32_t sA = sb + slot*GSTAGE;
        const uint32_t sB = sA + ATB;
        #pragma unroll
        for (int ks = 0; ks < 4; ks++) {
            const int acol = ks*16 + acolb;
            const int bcol = ks*16 + bcolb;
            uint32_t af[2][4];
            #pragma unroll
            for (int mi = 0; mi < 2; mi++)
                ldsm4(af[mi], sA + ((arow + mi*16) * GSTR + acol) * 2);
            #pragma unroll
            for (int jp = 0; jp < JP; jp++) {
                uint32_t bf[4];
                ldsm4(bf, sB + ((brow + jp*16) * GSTR + bcol) * 2);
                const int j2 = 2*jp;
                #pragma unroll
                for (int mi = 0; mi < 2; mi++) {
                    mma16816(acc[mi][j2],   af[mi], bf[0], bf[1]);
                    mma16816(acc[mi][j2+1], af[mi], bf[2], bf[3]);
                }
            }
        }
        if (++slot == STAGES) slot = 0;
    }
    __syncthreads();
}

// GEMM 1 (3-stage ring): qkv -> Q (pre-scaled) / K / V single fp16, [bh, n, hd]
__global__ __launch_bounds__(256,2) void qkv_tc_kernel() {
    extern __shared__ char sm[];
    const int bm = blockIdx.y, bn = blockIdx.x;
    float acc[2][8][4] = {};
    gemm_core<128,3>(g_x + (size_t)bm*128*CDIM, g_wq + (size_t)bn*128*CDIM,
                     smem_u32(sm), acc);

    const int wid = threadIdx.x >> 5, lane = threadIdx.x & 31;
    const int wm = wid >> 1, wn = wid & 1;
    const int g = lane >> 2, t2 = (lane & 3) << 1;
    const int ssel = bn / 6;
    const int h    = (bn % 6) * 2 + wn;
    __half* dst0 = (ssel==0 ? g_q : (ssel==1 ? g_k : g_v));
    const float qs = (ssel == 0) ? (SCALE * SM_LOG2E) : 1.0f;  // Q pre-scale
    #pragma unroll
    for (int mi = 0; mi < 2; mi++)
        #pragma unroll
        for (int half = 0; half < 2; half++) {
            int m = bm*128 + wm*32 + mi*16 + g + half*8;
            int b = m >> 10, n = m & 1023;
            size_t base = ((size_t)(b*HEADS + h) << 16) + ((size_t)n << 6);
            #pragma unroll
            for (int nj = 0; nj < 8; nj++) {
                int hd = nj*8 + t2;
                float f0 = half ? acc[mi][nj][2] : acc[mi][nj][0];
                float f1 = half ? acc[mi][nj][3] : acc[mi][nj][1];
                *(uint32_t*)&dst0[base + hd] = rnd2h(f0*qs, f1*qs);
            }
        }
}

// GEMM 3 (NB=64, 3-stage): out = att @ w_proj^T + bias, grid (12, 64)
__global__ __launch_bounds__(256,2) void proj_tc_kernel(const float* __restrict__ bias,
                                                        float* __restrict__ out) {
    extern __shared__ char sm[];
    const int bm = blockIdx.y, bn = blockIdx.x;
    float acc[2][4][4] = {};
    gemm_core<64,3>(g_a + (size_t)bm*128*CDIM, g_wp + (size_t)bn*64*CDIM,
                    smem_u32(sm), acc);

    const int wid = threadIdx.x >> 5, lane = threadIdx.x & 31;
    const int wm = wid >> 1, wn = wid & 1;
    const int g = lane >> 2, t2 = (lane & 3) << 1;
    #pragma unroll
    for (int nj = 0; nj < 4; nj++) {
        int d = bn*64 + wn*32 + nj*8 + t2;
        float2 bb = *(const float2*)(bias + d);
        #pragma unroll
        for (int mi = 0; mi < 2; mi++)
            #pragma unroll
            for (int half = 0; half < 2; half++) {
                int m = bm*128 + wm*32 + mi*16 + g + half*8;
                float2 v = half ? make_float2(acc[mi][nj][2]+bb.x, acc[mi][nj][3]+bb.y)
                                : make_float2(acc[mi][nj][0]+bb.x, acc[mi][nj][1]+bb.y);
                *(float2*)(out + (size_t)m*CDIM + d) = v;
            }
    }
}

// ---------------------------------------------------------------------------
// Flash attention, no online max. Q pre-scaled -> S already in exp2 domain.
// P = rnd_fp16(exp2f(S)); row sums via ones-B MMA.
// Br=128, Bc=64; 5-stage KV ring (4 in flight), one sync per kt.
// ---------------------------------------------------------------------------
#define ASTR  72
#define AQT   (128*ASTR*2)     // 18432
#define AKT   (64*ASTR*2)      // 9216
#define ASTG  (2*AKT)          // 18432
#define NKV   5
#define HONES 0x3C003C00u      // half2(1.0, 1.0)

__device__ __forceinline__ void stage_q1(uint32_t sq, const __half* q) {
    const int tid = threadIdx.x;
    #pragma unroll
    for (int rep = 0; rep < 4; rep++) {
        int idx = tid + rep*256;
        int row = idx >> 3, cp = idx & 7;
        cpa16(sq + row*(ASTR*2) + cp*16, q + ((size_t)row << 6) + cp*8);
    }
}
__device__ __forceinline__ void stage_kv(uint32_t skv, const __half* k, const __half* v, int kt) {
    const int tid = threadIdx.x;
    #pragma unroll
    for (int rep = 0; rep < 2; rep++) {
        int idx = tid + rep*256;
        int row = idx >> 3, cp = idx & 7;
        size_t so = (((size_t)(kt*64 + row)) << 6) + cp*8;
        uint32_t d = skv + row*(ASTR*2) + cp*16;
        cpa16(d,       k + so);
        cpa16(d + AKT, v + so);
    }
}

__global__ __launch_bounds__(256,2) void attn_tc_kernel() {
    extern __shared__ char sm[];
    uint32_t sb = smem_u32(sm);
    const uint32_t sQ  = sb;
    const uint32_t sKV = sb + AQT;

    const int qt = blockIdx.x, bh = blockIdx.y;
    const int tid = threadIdx.x, w = tid >> 5, lane = tid & 31;
    const int g = lane >> 2, t2 = (lane & 3) << 1;

    const size_t bhoff = (size_t)bh << 16;
    const __half* qp = g_q + bhoff + ((size_t)qt << 13);
    const __half* kp = g_k + bhoff;
    const __half* vp = g_v + bhoff;

    stage_q1(sQ, qp);
    stage_kv(sKV, kp, vp, 0);
    CP_COMMIT();
    stage_kv(sKV + ASTG, kp, vp, 1);
    CP_COMMIT();
    stage_kv(sKV + 2*ASTG, kp, vp, 2);
    CP_COMMIT();
    stage_kv(sKV + 3*ASTG, kp, vp, 3);
    CP_COMMIT();

    const int arow   = w*16 + (lane & 15);
    const int acolb  = (lane >> 4) << 3;
    const int brow_b = ((lane >> 4) << 3) + (lane & 7);
    const int bcolb  = ((lane >> 3) & 1) << 3;
    const int vrow_b = (lane & 15);
    const int vcolb  = (lane >> 4) << 3;

    float o[8][4] = {};
    float osum[4] = {};            // ones-column row-sum accumulators

    int ring = 0;
    for (int kt = 0; kt < 16; kt++) {
        if (kt + 4 < 16) { CP_WAIT(3); } else { CP_WAIT(0); }
        __syncthreads();
        if (kt + 4 < 16) {
            int wslot = ring + 4; if (wslot >= NKV) wslot -= NKV;
            stage_kv(sKV + wslot*ASTG, kp, vp, kt + 4);
            CP_COMMIT();
        }
        const uint32_t sK = sKV + ring*ASTG;
        const uint32_t sV = sK + AKT;

        // ---- S = Q K^T (Q pre-scaled; S in exp2 domain) ----
        float s[8][4];
        #pragma unroll
        for (int j = 0; j < 8; j++)
            { s[j][0]=0.f; s[j][1]=0.f; s[j][2]=0.f; s[j][3]=0.f; }
        #pragma unroll
        for (int ks = 0; ks < 4; ks++) {
            uint32_t qf[4];
            ldsm4(qf, sQ + (arow * ASTR + ks*16 + acolb) * 2);
            #pragma unroll
            for (int jp = 0; jp < 4; jp++) {
                uint32_t kf[4];
                ldsm4(kf, sK + ((brow_b + jp*16) * ASTR + ks*16 + bcolb) * 2);
                const int j2 = 2*jp;
                mma16816(s[j2],   qf, kf[0], kf[1]);
                mma16816(s[j2+1], qf, kf[2], kf[3]);
            }
        }

        // ---- P = fp16(exp2f(S)); row sums via ones MMA; O += P V ----
        #pragma unroll
        for (int kk = 0; kk < 4; kk++) {
            const int j0 = 2*kk, j1 = 2*kk+1;
            uint32_t pA[4];
            pA[0] = rnd2h(exp2f(s[j0][0]), exp2f(s[j0][1]));
            pA[1] = rnd2h(exp2f(s[j0][2]), exp2f(s[j0][3]));
            pA[2] = rnd2h(exp2f(s[j1][0]), exp2f(s[j1][1]));
            pA[3] = rnd2h(exp2f(s[j1][2]), exp2f(s[j1][3]));
            mma16816(osum, pA, HONES, HONES);    // exact fp32 row sums of P
            #pragma unroll
            for (int jp = 0; jp < 4; jp++) {
                uint32_t vf[4];
                ldsm4t(vf, sV + ((vrow_b + kk*16) * ASTR + jp*16 + vcolb) * 2);
                const int j2 = 2*jp;
                mma16816(o[j2],   pA, vf[0], vf[1]);
                mma16816(o[j2+1], pA, vf[2], vf[3]);
            }
        }
        if (++ring == NKV) ring = 0;
    }

    // ---- normalize + write fp16 att ----
    const int b = bh / HEADS, h = bh % HEADS;
    const float inv0 = 1.0f / osum[0], inv1 = 1.0f / osum[2];
    const int n0 = qt*128 + w*16 + g;
    size_t base0 = ((size_t)(b*SEQ + n0))*CDIM + h*HDIM;
    size_t base1 = base0 + (size_t)8*CDIM;
    #pragma unroll
    for (int nj = 0; nj < 8; nj++) {
        int hd = nj*8 + t2;
        *(uint32_t*)&g_a[base0 + hd] = rnd2h(o[nj][0]*inv0, o[nj][1]*inv0);
        *(uint32_t*)&g_a[base1 + hd] = rnd2h(o[nj][2]*inv1, o[nj][3]*inv1);
    }
}

// ---------------------------------------------------------------------------
extern "C" void kernel_launch(void* const* d_in, const int* in_sizes, int n_in,
                              void* d_out, int out_size) {
    const float* x = nullptr; const float* w_qkv = nullptr;
    const float* w_proj = nullptr; const float* b_proj = nullptr;
    for (int i = 0; i < n_in; i++) {
        switch (in_sizes[i]) {
            case BATCH*SEQ*CDIM: x      = (const float*)d_in[i]; break;
            case 3*CDIM*CDIM:    w_qkv  = (const float*)d_in[i]; break;
            case CDIM*CDIM:      w_proj = (const float*)d_in[i]; break;
            case CDIM:           b_proj = (const float*)d_in[i]; break;
        }
    }
    float* out = (float*)d_out;

    const int qkv_smem  = 3*(ATB + 128*GSTR*2);   // 110592 (2 CTAs/SM)
    const int proj_smem = 3*(ATB + 64*GSTR*2);    // 82944  (2 CTAs/SM)
    const int attn_smem = AQT + NKV*ASTG;         // 110592 (2 CTAs/SM)

    static void *xp=nullptr,*wq,*wp;
    if (!xp) {
        cudaGetSymbolAddress(&xp, g_x);
        cudaGetSymbolAddress(&wq, g_wq); cudaGetSymbolAddress(&wp, g_wp);
        cudaFuncSetAttribute(qkv_tc_kernel,  cudaFuncAttributeMaxDynamicSharedMemorySize, qkv_smem);
        cudaFuncSetAttribute(proj_tc_kernel, cudaFuncAttributeMaxDynamicSharedMemorySize, proj_smem);
        cudaFuncSetAttribute(attn_tc_kernel, cudaFuncAttributeMaxDynamicSharedMemorySize, attn_smem);
    }

    const int total4 = NX4 + NWQ4 + NWP4;
    round_all_kernel<<<(total4 + 255)/256, 256>>>(
        (const float4*)x, (const float4*)w_qkv, (const float4*)w_proj,
        (uint64_t*)xp, (uint64_t*)wq, (uint64_t*)wp);

    qkv_tc_kernel<<<dim3(18, 64), 256, qkv_smem>>>();
    attn_tc_kernel<<<dim3(8, 96), 256, attn_smem>>>();
    proj_tc_kernel<<<dim3(12, 64), 256, proj_smem>>>(b_proj, out);
}

// round 16
// speedup vs baseline: 1.0466x; 1.0466x over previous
#include <cuda_runtime.h>
#include <cuda_fp16.h>
#include <cstdint>

// Problem constants: B=8, N=1024, C=768, H=12, HD=64
#define BATCH 8
#define SEQ   1024
#define CDIM  768
#define HEADS 12
#define HDIM  64
#define SCALE 0.125f
#define SM_LOG2E 1.4426950408889634f

// ---------------------------------------------------------------------------
// Persistent fp16 scratch (no cudaMalloc anywhere)
// ---------------------------------------------------------------------------
__device__ __half g_x [BATCH*SEQ*CDIM];
__device__ __half g_wq[3*CDIM*CDIM];
__device__ __half g_wp[CDIM*CDIM];
__device__ __half g_q [BATCH*HEADS*SEQ*HDIM];   // pre-scaled by SCALE*log2(e)
__device__ __half g_k [BATCH*HEADS*SEQ*HDIM];
__device__ __half g_v [BATCH*HEADS*SEQ*HDIM];
__device__ __half g_a [BATCH*SEQ*CDIM];

// ---------------------------------------------------------------------------
// helpers
// ---------------------------------------------------------------------------
__device__ __forceinline__ uint32_t smem_u32(const void* p) {
    uint32_t a;
    asm("{ .reg .u64 t; cvta.to.shared.u64 t, %1; cvt.u32.u64 %0, t; }" : "=r"(a) : "l"(p));
    return a;
}
__device__ __forceinline__ void cpa16(uint32_t dst, const void* src) {
    asm volatile("cp.async.cg.shared.global [%0], [%1], 16;"
                 :: "r"(dst), "l"(__cvta_generic_to_global(src)) : "memory");
}
#define CP_COMMIT() asm volatile("cp.async.commit_group;" ::: "memory")
#define CP_WAIT(n)  asm volatile("cp.async.wait_group %0;" :: "n"(n) : "memory")

__device__ __forceinline__ void ldsm4(uint32_t* r, uint32_t a) {
    asm volatile("ldmatrix.sync.aligned.m8n8.x4.shared.b16 {%0,%1,%2,%3}, [%4];"
                 : "=r"(r[0]), "=r"(r[1]), "=r"(r[2]), "=r"(r[3]) : "r"(a));
}
__device__ __forceinline__ void ldsm4t(uint32_t* r, uint32_t a) {
    asm volatile("ldmatrix.sync.aligned.m8n8.x4.trans.shared.b16 {%0,%1,%2,%3}, [%4];"
                 : "=r"(r[0]), "=r"(r[1]), "=r"(r[2]), "=r"(r[3]) : "r"(a));
}
__device__ __forceinline__ void mma16816(float* d, const uint32_t* a, uint32_t b0, uint32_t b1) {
    asm volatile("mma.sync.aligned.m16n8k16.row.col.f32.f16.f16.f32 "
                 "{%0,%1,%2,%3}, {%4,%5,%6,%7}, {%8,%9}, {%0,%1,%2,%3};"
                 : "+f"(d[0]), "+f"(d[1]), "+f"(d[2]), "+f"(d[3])
                 : "r"(a[0]), "r"(a[1]), "r"(a[2]), "r"(a[3]), "r"(b0), "r"(b1));
}
__device__ __forceinline__ uint32_t rnd2h(float a, float b) {
    __half2 h = __floats2half2_rn(a, b);
    return *(uint32_t*)&h;
}

// ---------------------------------------------------------------------------
// Fused conversion kernel: all three fp32 -> fp16 conversions in one launch
// ---------------------------------------------------------------------------
#define NX4  (BATCH*SEQ*CDIM/4)     // 1572864
#define NWQ4 (3*CDIM*CDIM/4)        // 442368
#define NWP4 (CDIM*CDIM/4)          // 147456

__global__ __launch_bounds__(256) void round_all_kernel(
        const float4* __restrict__ x, const float4* __restrict__ wq,
        const float4* __restrict__ wp,
        uint64_t* __restrict__ dx, uint64_t* __restrict__ dwq,
        uint64_t* __restrict__ dwp) {
    int i = blockIdx.x*blockDim.x + threadIdx.x;
    const float4* src; uint64_t* dst; int j;
    if (i < NX4)                 { src = x;  dst = dx;  j = i; }
    else if (i < NX4 + NWQ4)     { src = wq; dst = dwq; j = i - NX4; }
    else if (i < NX4+NWQ4+NWP4)  { src = wp; dst = dwp; j = i - NX4 - NWQ4; }
    else return;
    float4 v = src[j];
    dst[j] = ((uint64_t)rnd2h(v.z, v.w) << 32) | rnd2h(v.x, v.y);
}

// ---------------------------------------------------------------------------
// GEMM core: D[128xNB] = A16[128x768] * B16[NBx768]^T, BK=64, STAGES-deep
// cp.async ring, ONE __syncthreads per chunk. Single-product fp16.
// ---------------------------------------------------------------------------
#define GSTR 72
#define ATB  (128*GSTR*2)   // 18432 B per 128-row tile

template<int NB>
__device__ __forceinline__ void stage_gemm(uint32_t sbuf,
        const __half* A_g, const __half* B_g, int c) {
    const int tid = threadIdx.x;
    #pragma unroll
    for (int rep = 0; rep < 4; rep++) {
        int idx = tid + rep*256;
        int row = idx >> 3, cp = idx & 7;
        size_t so = (size_t)row*CDIM + c*64 + cp*8;
        cpa16(sbuf + row*(GSTR*2) + cp*16, A_g + so);
    }
    #pragma unroll
    for (int rep = 0; rep < NB/32; rep++) {
        int idx = tid + rep*256;
        int row = idx >> 3, cp = idx & 7;
        size_t so = (size_t)row*CDIM + c*64 + cp*8;
        cpa16(sbuf + ATB + row*(GSTR*2) + cp*16, B_g + so);
    }
}

template<int NB, int STAGES>
__device__ __forceinline__ void gemm_core(const __half* A_g, const __half* B_g,
                                          uint32_t sb, float acc[2][NB/16][4]) {
    constexpr int JP  = NB/32;
    constexpr int BTB = NB * GSTR * 2;
    constexpr int GSTAGE = ATB + BTB;
    const int tid = threadIdx.x;
    const int wid = tid >> 5, lane = tid & 31;
    const int wm = wid >> 1, wn = wid & 1;
    const int arow  = wm*32 + (lane & 15);
    const int acolb = (lane >> 4) << 3;
    const int brow  = wn*(NB/2) + ((lane >> 4) << 3) + (lane & 7);
    const int bcolb = ((lane >> 3) & 1) << 3;

    #pragma unroll
    for (int p = 0; p < STAGES - 1; p++) {
        stage_gemm<NB>(sb + p*GSTAGE, A_g, B_g, p);
        CP_COMMIT();
    }

    int slot = 0;
    for (int c = 0; c < 12; c++) {
        if (c + STAGES - 1 < 12) { CP_WAIT(STAGES - 2); } else { CP_WAIT(0); }
        __syncthreads();
        const int pre = c + STAGES - 1;
        if (pre < 12) {
            int ws = slot + STAGES - 1; if (ws >= STAGES) ws -= STAGES;
            stage_gemm<NB>(sb + ws*GSTAGE, A_g, B_g, pre);
            CP_COMMIT();
        }

        const uint32_t sA = sb + slot*GSTAGE;
        const uint32_t sB = sA + ATB;
        #pragma unroll
        for (int ks = 0; ks < 4; ks++) {
            const int acol = ks*16 + acolb;
            const int bcol = ks*16 + bcolb;
            uint32_t af[2][4];
            #pragma unroll
            for (int mi = 0; mi < 2; mi++)
                ldsm4(af[mi], sA + ((arow + mi*16) * GSTR + acol) * 2);
            #pragma unroll
            for (int jp = 0; jp < JP; jp++) {
                uint32_t bf[4];
                ldsm4(bf, sB + ((brow + jp*16) * GSTR + bcol) * 2);
                const int j2 = 2*jp;
                #pragma unroll
                for (int mi = 0; mi < 2; mi++) {
                    mma16816(acc[mi][j2],   af[mi], bf[0], bf[1]);
                    mma16816(acc[mi][j2+1], af[mi], bf[2], bf[3]);
                }
            }
        }
        if (++slot == STAGES) slot = 0;
    }
    __syncthreads();
}

// GEMM 1 (3-stage ring): qkv -> Q (pre-scaled) / K / V single fp16, [bh, n, hd]
__global__ __launch_bounds__(256,2) void qkv_tc_kernel() {
    extern __shared__ char sm[];
    const int bm = blockIdx.y, bn = blockIdx.x;
    float acc[2][8][4] = {};
    gemm_core<128,3>(g_x + (size_t)bm*128*CDIM, g_wq + (size_t)bn*128*CDIM,
                     smem_u32(sm), acc);

    const int wid = threadIdx.x >> 5, lane = threadIdx.x & 31;
    const int wm = wid >> 1, wn = wid & 1;
    const int g = lane >> 2, t2 = (lane & 3) << 1;
    const int ssel = bn / 6;
    const int h    = (bn % 6) * 2 + wn;
    __half* dst0 = (ssel==0 ? g_q : (ssel==1 ? g_k : g_v));
    const float qs = (ssel == 0) ? (SCALE * SM_LOG2E) : 1.0f;  // Q pre-scale
    #pragma unroll
    for (int mi = 0; mi < 2; mi++)
        #pragma unroll
        for (int half = 0; half < 2; half++) {
            int m = bm*128 + wm*32 + mi*16 + g + half*8;
            int b = m >> 10, n = m & 1023;
            size_t base = ((size_t)(b*HEADS + h) << 16) + ((size_t)n << 6);
            #pragma unroll
            for (int nj = 0; nj < 8; nj++) {
                int hd = nj*8 + t2;
                float f0 = half ? acc[mi][nj][2] : acc[mi][nj][0];
                float f1 = half ? acc[mi][nj][3] : acc[mi][nj][1];
                *(uint32_t*)&dst0[base + hd] = rnd2h(f0*qs, f1*qs);
            }
        }
}

// GEMM 3 (NB=128, 3-stage): out = att @ w_proj^T + bias, grid (6, 64)
__global__ __launch_bounds__(256,2) void proj_tc_kernel(const float* __restrict__ bias,
                                                        float* __restrict__ out) {
    extern __shared__ char sm[];
    const int bm = blockIdx.y, bn = blockIdx.x;
    float acc[2][8][4] = {};
    gemm_core<128,3>(g_a + (size_t)bm*128*CDIM, g_wp + (size_t)bn*128*CDIM,
                     smem_u32(sm), acc);

    const int wid = threadIdx.x >> 5, lane = threadIdx.x & 31;
    const int wm = wid >> 1, wn = wid & 1;
    const int g = lane >> 2, t2 = (lane & 3) << 1;
    #pragma unroll
    for (int nj = 0; nj < 8; nj++) {
        int d = bn*128 + wn*64 + nj*8 + t2;
        float2 bb = *(const float2*)(bias + d);
        #pragma unroll
        for (int mi = 0; mi < 2; mi++)
            #pragma unroll
            for (int half = 0; half < 2; half++) {
                int m = bm*128 + wm*32 + mi*16 + g + half*8;
                float2 v = half ? make_float2(acc[mi][nj][2]+bb.x, acc[mi][nj][3]+bb.y)
                                : make_float2(acc[mi][nj][0]+bb.x, acc[mi][nj][1]+bb.y);
                *(float2*)(out + (size_t)m*CDIM + d) = v;
            }
    }
}

// ---------------------------------------------------------------------------
// Flash attention, no online max. Q pre-scaled -> S already in exp2 domain.
// Q fragments HOISTED into registers (loop-invariant). P = fp16(exp2f(S));
// row sums via ones-B MMA. Br=128, Bc=64; 4-stage KV ring, one sync per kt.
// ---------------------------------------------------------------------------
#define ASTR  72
#define AQT   (128*ASTR*2)     // 18432
#define AKT   (64*ASTR*2)      // 9216
#define ASTG  (2*AKT)          // 18432
#define NKV   4
#define HONES 0x3C003C00u      // half2(1.0, 1.0)

__device__ __forceinline__ void stage_q1(uint32_t sq, const __half* q) {
    const int tid = threadIdx.x;
    #pragma unroll
    for (int rep = 0; rep < 4; rep++) {
        int idx = tid + rep*256;
        int row = idx >> 3, cp = idx & 7;
        cpa16(sq + row*(ASTR*2) + cp*16, q + ((size_t)row << 6) + cp*8);
    }
}
__device__ __forceinline__ void stage_kv(uint32_t skv, const __half* k, const __half* v, int kt) {
    const int tid = threadIdx.x;
    #pragma unroll
    for (int rep = 0; rep < 2; rep++) {
        int idx = tid + rep*256;
        int row = idx >> 3, cp = idx & 7;
        size_t so = (((size_t)(kt*64 + row)) << 6) + cp*8;
        uint32_t d = skv + row*(ASTR*2) + cp*16;
        cpa16(d,       k + so);
        cpa16(d + AKT, v + so);
    }
}

__global__ __launch_bounds__(256,2) void attn_tc_kernel() {
    extern __shared__ char sm[];
    uint32_t sb = smem_u32(sm);
    const uint32_t sQ  = sb;
    const uint32_t sKV = sb + AQT;

    const int qt = blockIdx.x, bh = blockIdx.y;
    const int tid = threadIdx.x, w = tid >> 5, lane = tid & 31;
    const int g = lane >> 2, t2 = (lane & 3) << 1;

    const size_t bhoff = (size_t)bh << 16;
    const __half* qp = g_q + bhoff + ((size_t)qt << 13);
    const __half* kp = g_k + bhoff;
    const __half* vp = g_v + bhoff;

    stage_q1(sQ, qp);
    stage_kv(sKV, kp, vp, 0);
    CP_COMMIT();                      // group: Q + kv0
    stage_kv(sKV + ASTG, kp, vp, 1);
    CP_COMMIT();
    stage_kv(sKV + 2*ASTG, kp, vp, 2);
    CP_COMMIT();

    const int arow   = w*16 + (lane & 15);
    const int acolb  = (lane >> 4) << 3;
    const int brow_b = ((lane >> 4) << 3) + (lane & 7);
    const int bcolb  = ((lane >> 3) & 1) << 3;
    const int vrow_b = (lane & 15);
    const int vcolb  = (lane >> 4) << 3;

    float o[8][4] = {};
    float osum[4] = {};               // ones-column row-sum accumulators
    uint32_t qreg[4][4];              // hoisted Q fragments (loop-invariant)
    bool qloaded = false;

    int ring = 0;
    for (int kt = 0; kt < 16; kt++) {
        if (kt + 3 < 16) { CP_WAIT(2); } else { CP_WAIT(0); }
        __syncthreads();
        if (kt + 3 < 16) {
            int wslot = ring + 3; if (wslot >= NKV) wslot -= NKV;
            stage_kv(sKV + wslot*ASTG, kp, vp, kt + 3);
            CP_COMMIT();
        }
        if (!qloaded) {               // first iteration: Q is resident (group 0)
            #pragma unroll
            for (int ks = 0; ks < 4; ks++)
                ldsm4(qreg[ks], sQ + (arow * ASTR + ks*16 + acolb) * 2);
            qloaded = true;
        }
        const uint32_t sK = sKV + ring*ASTG;
        const uint32_t sV = sK + AKT;

        // ---- S = Q K^T (Q pre-scaled; S in exp2 domain) ----
        float s[8][4];
        #pragma unroll
        for (int j = 0; j < 8; j++)
            { s[j][0]=0.f; s[j][1]=0.f; s[j][2]=0.f; s[j][3]=0.f; }
        #pragma unroll
        for (int ks = 0; ks < 4; ks++) {
            #pragma unroll
            for (int jp = 0; jp < 4; jp++) {
                uint32_t kf[4];
                ldsm4(kf, sK + ((brow_b + jp*16) * ASTR + ks*16 + bcolb) * 2);
                const int j2 = 2*jp;
                mma16816(s[j2],   qreg[ks], kf[0], kf[1]);
                mma16816(s[j2+1], qreg[ks], kf[2], kf[3]);
            }
        }

        // ---- P = fp16(exp2f(S)); row sums via ones MMA; O += P V ----
        #pragma unroll
        for (int kk = 0; kk < 4; kk++) {
            const int j0 = 2*kk, j1 = 2*kk+1;
            uint32_t pA[4];
            pA[0] = rnd2h(exp2f(s[j0][0]), exp2f(s[j0][1]));
            pA[1] = rnd2h(exp2f(s[j0][2]), exp2f(s[j0][3]));
            pA[2] = rnd2h(exp2f(s[j1][0]), exp2f(s[j1][1]));
            pA[3] = rnd2h(exp2f(s[j1][2]), exp2f(s[j1][3]));
            mma16816(osum, pA, HONES, HONES);    // exact fp32 row sums of P
            #pragma unroll
            for (int jp = 0; jp < 4; jp++) {
                uint32_t vf[4];
                ldsm4t(vf, sV + ((vrow_b + kk*16) * ASTR + jp*16 + vcolb) * 2);
                const int j2 = 2*jp;
                mma16816(o[j2],   pA, vf[0], vf[1]);
                mma16816(o[j2+1], pA, vf[2], vf[3]);
            }
        }
        if (++ring == NKV) ring = 0;
    }

    // ---- normalize + write fp16 att ----
    const int b = bh / HEADS, h = bh % HEADS;
    const float inv0 = 1.0f / osum[0], inv1 = 1.0f / osum[2];
    const int n0 = qt*128 + w*16 + g;
    size_t base0 = ((size_t)(b*SEQ + n0))*CDIM + h*HDIM;
    size_t base1 = base0 + (size_t)8*CDIM;
    #pragma unroll
    for (int nj = 0; nj < 8; nj++) {
        int hd = nj*8 + t2;
        *(uint32_t*)&g_a[base0 + hd] = rnd2h(o[nj][0]*inv0, o[nj][1]*inv0);
        *(uint32_t*)&g_a[base1 + hd] = rnd2h(o[nj][2]*inv1, o[nj][3]*inv1);
    }
}

// ---------------------------------------------------------------------------
extern "C" void kernel_launch(void* const* d_in, const int* in_sizes, int n_in,
                              void* d_out, int out_size) {
    const float* x = nullptr; const float* w_qkv = nullptr;
    const float* w_proj = nullptr; const float* b_proj = nullptr;
    for (int i = 0; i < n_in; i++) {
        switch (in_sizes[i]) {
            case BATCH*SEQ*CDIM: x      = (const float*)d_in[i]; break;
            case 3*CDIM*CDIM:    w_qkv  = (const float*)d_in[i]; break;
            case CDIM*CDIM:      w_proj = (const float*)d_in[i]; break;
            case CDIM:           b_proj = (const float*)d_in[i]; break;
        }
    }
    float* out = (float*)d_out;

    const int gemm_smem = 3*(ATB + 128*GSTR*2);   // 110592 (2 CTAs/SM)
    const int attn_smem = AQT + NKV*ASTG;         // 92160  (2 CTAs/SM)

    static void *xp=nullptr,*wq,*wp;
    if (!xp) {
        cudaGetSymbolAddress(&xp, g_x);
        cudaGetSymbolAddress(&wq, g_wq); cudaGetSymbolAddress(&wp, g_wp);
        cudaFuncSetAttribute(qkv_tc_kernel,  cudaFuncAttributeMaxDynamicSharedMemorySize, gemm_smem);
        cudaFuncSetAttribute(proj_tc_kernel, cudaFuncAttributeMaxDynamicSharedMemorySize, gemm_smem);
        cudaFuncSetAttribute(attn_tc_kernel, cudaFuncAttributeMaxDynamicSharedMemorySize, attn_smem);
    }

    const int total4 = NX4 + NWQ4 + NWP4;
    round_all_kernel<<<(total4 + 255)/256, 256>>>(
        (const float4*)x, (const float4*)w_qkv, (const float4*)w_proj,
        (uint64_t*)xp, (uint64_t*)wq, (uint64_t*)wp);

    qkv_tc_kernel<<<dim3(18, 64), 256, gemm_smem>>>();
    attn_tc_kernel<<<dim3(8, 96), 256, attn_smem>>>();
    proj_tc_kernel<<<dim3(6, 64), 256, gemm_smem>>>(b_proj, out);
}

// round 17
// speedup vs baseline: 1.0485x; 1.0018x over previous
#include <cuda_runtime.h>
#include <cuda_fp16.h>
#include <cstdint>

// Problem constants: B=8, N=1024, C=768, H=12, HD=64
#define BATCH 8
#define SEQ   1024
#define CDIM  768
#define HEADS 12
#define HDIM  64
#define SCALE 0.125f
#define SM_LOG2E 1.4426950408889634f

// ---------------------------------------------------------------------------
// Persistent fp16 scratch (no cudaMalloc anywhere)
// ---------------------------------------------------------------------------
__device__ __half g_x [BATCH*SEQ*CDIM];
__device__ __half g_wq[3*CDIM*CDIM];
__device__ __half g_wp[CDIM*CDIM];
__device__ __half g_q [BATCH*HEADS*SEQ*HDIM];   // pre-scaled by SCALE*log2(e)
__device__ __half g_k [BATCH*HEADS*SEQ*HDIM];
__device__ __half g_v [BATCH*HEADS*SEQ*HDIM];
__device__ __half g_a [BATCH*SEQ*CDIM];

// ---------------------------------------------------------------------------
// helpers
// ---------------------------------------------------------------------------
__device__ __forceinline__ uint32_t smem_u32(const void* p) {
    uint32_t a;
    asm("{ .reg .u64 t; cvta.to.shared.u64 t, %1; cvt.u32.u64 %0, t; }" : "=r"(a) : "l"(p));
    return a;
}
__device__ __forceinline__ void cpa16(uint32_t dst, const void* src) {
    asm volatile("cp.async.cg.shared.global [%0], [%1], 16;"
                 :: "r"(dst), "l"(__cvta_generic_to_global(src)) : "memory");
}
#define CP_COMMIT() asm volatile("cp.async.commit_group;" ::: "memory")
#define CP_WAIT(n)  asm volatile("cp.async.wait_group %0;" :: "n"(n) : "memory")

__device__ __forceinline__ void ldsm4(uint32_t* r, uint32_t a) {
    asm volatile("ldmatrix.sync.aligned.m8n8.x4.shared.b16 {%0,%1,%2,%3}, [%4];"
                 : "=r"(r[0]), "=r"(r[1]), "=r"(r[2]), "=r"(r[3]) : "r"(a));
}
__device__ __forceinline__ void ldsm4t(uint32_t* r, uint32_t a) {
    asm volatile("ldmatrix.sync.aligned.m8n8.x4.trans.shared.b16 {%0,%1,%2,%3}, [%4];"
                 : "=r"(r[0]), "=r"(r[1]), "=r"(r[2]), "=r"(r[3]) : "r"(a));
}
__device__ __forceinline__ void mma16816(float* d, const uint32_t* a, uint32_t b0, uint32_t b1) {
    asm volatile("mma.sync.aligned.m16n8k16.row.col.f32.f16.f16.f32 "
                 "{%0,%1,%2,%3}, {%4,%5,%6,%7}, {%8,%9}, {%0,%1,%2,%3};"
                 : "+f"(d[0]), "+f"(d[1]), "+f"(d[2]), "+f"(d[3])
                 : "r"(a[0]), "r"(a[1]), "r"(a[2]), "r"(a[3]), "r"(b0), "r"(b1));
}
__device__ __forceinline__ uint32_t rnd2h(float a, float b) {
    __half2 h = __floats2half2_rn(a, b);
    return *(uint32_t*)&h;
}

// ---------------------------------------------------------------------------
// Fused conversion kernel: all three fp32 -> fp16 conversions in one launch
// ---------------------------------------------------------------------------
#define NX4  (BATCH*SEQ*CDIM/4)     // 1572864
#define NWQ4 (3*CDIM*CDIM/4)        // 442368
#define NWP4 (CDIM*CDIM/4)          // 147456

__global__ __launch_bounds__(256) void round_all_kernel(
        const float4* __restrict__ x, const float4* __restrict__ wq,
        const float4* __restrict__ wp,
        uint64_t* __restrict__ dx, uint64_t* __restrict__ dwq,
        uint64_t* __restrict__ dwp) {
    int i = blockIdx.x*blockDim.x + threadIdx.x;
    const float4* src; uint64_t* dst; int j;
    if (i < NX4)                 { src = x;  dst = dx;  j = i; }
    else if (i < NX4 + NWQ4)     { src = wq; dst = dwq; j = i - NX4; }
    else if (i < NX4+NWQ4+NWP4)  { src = wp; dst = dwp; j = i - NX4 - NWQ4; }
    else return;
    float4 v = src[j];
    dst[j] = ((uint64_t)rnd2h(v.z, v.w) << 32) | rnd2h(v.x, v.y);
}

// ---------------------------------------------------------------------------
// GEMM core: D[128xNB] = A16[128x768] * B16[NBx768]^T, BK=64, STAGES-deep
// cp.async ring, ONE __syncthreads per chunk. Fragment loads front-batched
// per k-slice (all ldsm issued before the MMA run) for latency overlap.
// ---------------------------------------------------------------------------
#define GSTR 72
#define ATB  (128*GSTR*2)   // 18432 B per 128-row tile

template<int NB>
__device__ __forceinline__ void stage_gemm(uint32_t sbuf,
        const __half* A_g, const __half* B_g, int c) {
    const int tid = threadIdx.x;
    #pragma unroll
    for (int rep = 0; rep < 4; rep++) {
        int idx = tid + rep*256;
        int row = idx >> 3, cp = idx & 7;
        size_t so = (size_t)row*CDIM + c*64 + cp*8;
        cpa16(sbuf + row*(GSTR*2) + cp*16, A_g + so);
    }
    #pragma unroll
    for (int rep = 0; rep < NB/32; rep++) {
        int idx = tid + rep*256;
        int row = idx >> 3, cp = idx & 7;
        size_t so = (size_t)row*CDIM + c*64 + cp*8;
        cpa16(sbuf + ATB + row*(GSTR*2) + cp*16, B_g + so);
    }
}

template<int NB, int STAGES>
__device__ __forceinline__ void gemm_core(const __half* A_g, const __half* B_g,
                                          uint32_t sb, float acc[2][NB/16][4]) {
    constexpr int JP  = NB/32;
    constexpr int BTB = NB * GSTR * 2;
    constexpr int GSTAGE = ATB + BTB;
    const int tid = threadIdx.x;
    const int wid = tid >> 5, lane = tid & 31;
    const int wm = wid >> 1, wn = wid & 1;
    const int arow  = wm*32 + (lane & 15);
    const int acolb = (lane >> 4) << 3;
    const int brow  = wn*(NB/2) + ((lane >> 4) << 3) + (lane & 7);
    const int bcolb = ((lane >> 3) & 1) << 3;

    #pragma unroll
    for (int p = 0; p < STAGES - 1; p++) {
        stage_gemm<NB>(sb + p*GSTAGE, A_g, B_g, p);
        CP_COMMIT();
    }

    int slot = 0;
    for (int c = 0; c < 12; c++) {
        if (c + STAGES - 1 < 12) { CP_WAIT(STAGES - 2); } else { CP_WAIT(0); }
        __syncthreads();
        const int pre = c + STAGES - 1;
        if (pre < 12) {
            int ws = slot + STAGES - 1; if (ws >= STAGES) ws -= STAGES;
            stage_gemm<NB>(sb + ws*GSTAGE, A_g, B_g, pre);
            CP_COMMIT();
        }

        const uint32_t sA = sb + slot*GSTAGE;
        const uint32_t sB = sA + ATB;
        #pragma unroll
        for (int ks = 0; ks < 4; ks++) {
            const int acol = ks*16 + acolb;
            const int bcol = ks*16 + bcolb;
            // front-batch ALL fragment loads of this k-slice
            uint32_t af[2][4], bf[JP][4];
            #pragma unroll
            for (int mi = 0; mi < 2; mi++)
                ldsm4(af[mi], sA + ((arow + mi*16) * GSTR + acol) * 2);
            #pragma unroll
            for (int jp = 0; jp < JP; jp++)
                ldsm4(bf[jp], sB + ((brow + jp*16) * GSTR + bcol) * 2);
            // dependency-free MMA run
            #pragma unroll
            for (int jp = 0; jp < JP; jp++) {
                const int j2 = 2*jp;
                #pragma unroll
                for (int mi = 0; mi < 2; mi++) {
                    mma16816(acc[mi][j2],   af[mi], bf[jp][0], bf[jp][1]);
                    mma16816(acc[mi][j2+1], af[mi], bf[jp][2], bf[jp][3]);
                }
            }
        }
        if (++slot == STAGES) slot = 0;
    }
    __syncthreads();
}

// GEMM 1 (3-stage ring): qkv -> Q (pre-scaled) / K / V single fp16, [bh, n, hd]
__global__ __launch_bounds__(256,2) void qkv_tc_kernel() {
    extern __shared__ char sm[];
    const int bm = blockIdx.y, bn = blockIdx.x;
    float acc[2][8][4] = {};
    gemm_core<128,3>(g_x + (size_t)bm*128*CDIM, g_wq + (size_t)bn*128*CDIM,
                     smem_u32(sm), acc);

    const int wid = threadIdx.x >> 5, lane = threadIdx.x & 31;
    const int wm = wid >> 1, wn = wid & 1;
    const int g = lane >> 2, t2 = (lane & 3) << 1;
    const int ssel = bn / 6;
    const int h    = (bn % 6) * 2 + wn;
    __half* dst0 = (ssel==0 ? g_q : (ssel==1 ? g_k : g_v));
    const float qs = (ssel == 0) ? (SCALE * SM_LOG2E) : 1.0f;  // Q pre-scale
    #pragma unroll
    for (int mi = 0; mi < 2; mi++)
        #pragma unroll
        for (int half = 0; half < 2; half++) {
            int m = bm*128 + wm*32 + mi*16 + g + half*8;
            int b = m >> 10, n = m & 1023;
            size_t base = ((size_t)(b*HEADS + h) << 16) + ((size_t)n << 6);
            #pragma unroll
            for (int nj = 0; nj < 8; nj++) {
                int hd = nj*8 + t2;
                float f0 = half ? acc[mi][nj][2] : acc[mi][nj][0];
                float f1 = half ? acc[mi][nj][3] : acc[mi][nj][1];
                *(uint32_t*)&dst0[base + hd] = rnd2h(f0*qs, f1*qs);
            }
        }
}

// GEMM 3 (NB=128, 3-stage): out = att @ w_proj^T + bias, grid (6, 64)
__global__ __launch_bounds__(256,2) void proj_tc_kernel(const float* __restrict__ bias,
                                                        float* __restrict__ out) {
    extern __shared__ char sm[];
    const int bm = blockIdx.y, bn = blockIdx.x;
    float acc[2][8][4] = {};
    gemm_core<128,3>(g_a + (size_t)bm*128*CDIM, g_wp + (size_t)bn*128*CDIM,
                     smem_u32(sm), acc);

    const int wid = threadIdx.x >> 5, lane = threadIdx.x & 31;
    const int wm = wid >> 1, wn = wid & 1;
    const int g = lane >> 2, t2 = (lane & 3) << 1;
    #pragma unroll
    for (int nj = 0; nj < 8; nj++) {
        int d = bn*128 + wn*64 + nj*8 + t2;
        float2 bb = *(const float2*)(bias + d);
        #pragma unroll
        for (int mi = 0; mi < 2; mi++)
            #pragma unroll
            for (int half = 0; half < 2; half++) {
                int m = bm*128 + wm*32 + mi*16 + g + half*8;
                float2 v = half ? make_float2(acc[mi][nj][2]+bb.x, acc[mi][nj][3]+bb.y)
                                : make_float2(acc[mi][nj][0]+bb.x, acc[mi][nj][1]+bb.y);
                *(float2*)(out + (size_t)m*CDIM + d) = v;
            }
    }
}

// ---------------------------------------------------------------------------
// Flash attention, no online max. Q pre-scaled -> S already in exp2 domain.
// Q fragments hoisted; K/V fragment loads front-batched; exp for whole kt
// batched into pA before the PV MMA run. Br=128, Bc=64; 4-stage KV ring.
// ---------------------------------------------------------------------------
#define ASTR  72
#define AQT   (128*ASTR*2)     // 18432
#define AKT   (64*ASTR*2)      // 9216
#define ASTG  (2*AKT)          // 18432
#define NKV   4
#define HONES 0x3C003C00u      // half2(1.0, 1.0)

__device__ __forceinline__ void stage_q1(uint32_t sq, const __half* q) {
    const int tid = threadIdx.x;
    #pragma unroll
    for (int rep = 0; rep < 4; rep++) {
        int idx = tid + rep*256;
        int row = idx >> 3, cp = idx & 7;
        cpa16(sq + row*(ASTR*2) + cp*16, q + ((size_t)row << 6) + cp*8);
    }
}
__device__ __forceinline__ void stage_kv(uint32_t skv, const __half* k, const __half* v, int kt) {
    const int tid = threadIdx.x;
    #pragma unroll
    for (int rep = 0; rep < 2; rep++) {
        int idx = tid + rep*256;
        int row = idx >> 3, cp = idx & 7;
        size_t so = (((size_t)(kt*64 + row)) << 6) + cp*8;
        uint32_t d = skv + row*(ASTR*2) + cp*16;
        cpa16(d,       k + so);
        cpa16(d + AKT, v + so);
    }
}

__global__ __launch_bounds__(256,2) void attn_tc_kernel() {
    extern __shared__ char sm[];
    uint32_t sb = smem_u32(sm);
    const uint32_t sQ  = sb;
    const uint32_t sKV = sb + AQT;

    const int qt = blockIdx.x, bh = blockIdx.y;
    const int tid = threadIdx.x, w = tid >> 5, lane = tid & 31;
    const int g = lane >> 2, t2 = (lane & 3) << 1;

    const size_t bhoff = (size_t)bh << 16;
    const __half* qp = g_q + bhoff + ((size_t)qt << 13);
    const __half* kp = g_k + bhoff;
    const __half* vp = g_v + bhoff;

    stage_q1(sQ, qp);
    stage_kv(sKV, kp, vp, 0);
    CP_COMMIT();                      // group: Q + kv0
    stage_kv(sKV + ASTG, kp, vp, 1);
    CP_COMMIT();
    stage_kv(sKV + 2*ASTG, kp, vp, 2);
    CP_COMMIT();

    const int arow   = w*16 + (lane & 15);
    const int acolb  = (lane >> 4) << 3;
    const int brow_b = ((lane >> 4) << 3) + (lane & 7);
    const int bcolb  = ((lane >> 3) & 1) << 3;
    const int vrow_b = (lane & 15);
    const int vcolb  = (lane >> 4) << 3;

    float o[8][4] = {};
    float osum[4] = {};               // ones-column row-sum accumulators
    uint32_t qreg[4][4];              // hoisted Q fragments (loop-invariant)
    bool qloaded = false;

    int ring = 0;
    for (int kt = 0; kt < 16; kt++) {
        if (kt + 3 < 16) { CP_WAIT(2); } else { CP_WAIT(0); }
        __syncthreads();
        if (kt + 3 < 16) {
            int wslot = ring + 3; if (wslot >= NKV) wslot -= NKV;
            stage_kv(sKV + wslot*ASTG, kp, vp, kt + 3);
            CP_COMMIT();
        }
        if (!qloaded) {               // first iteration: Q is resident (group 0)
            #pragma unroll
            for (int ks = 0; ks < 4; ks++)
                ldsm4(qreg[ks], sQ + (arow * ASTR + ks*16 + acolb) * 2);
            qloaded = true;
        }
        const uint32_t sK = sKV + ring*ASTG;
        const uint32_t sV = sK + AKT;

        // ---- S = Q K^T (K fragments front-batched per k-slice) ----
        float s[8][4];
        #pragma unroll
        for (int j = 0; j < 8; j++)
            { s[j][0]=0.f; s[j][1]=0.f; s[j][2]=0.f; s[j][3]=0.f; }
        #pragma unroll
        for (int ks = 0; ks < 4; ks++) {
            uint32_t kf[4][4];
            #pragma unroll
            for (int jp = 0; jp < 4; jp++)
                ldsm4(kf[jp], sK + ((brow_b + jp*16) * ASTR + ks*16 + bcolb) * 2);
            #pragma unroll
            for (int jp = 0; jp < 4; jp++) {
                const int j2 = 2*jp;
                mma16816(s[j2],   qreg[ks], kf[jp][0], kf[jp][1]);
                mma16816(s[j2+1], qreg[ks], kf[jp][2], kf[jp][3]);
            }
        }

        // ---- exp for the whole kt, then row sums via ones MMA ----
        uint32_t pA[4][4];
        #pragma unroll
        for (int kk = 0; kk < 4; kk++) {
            const int j0 = 2*kk, j1 = 2*kk+1;
            pA[kk][0] = rnd2h(exp2f(s[j0][0]), exp2f(s[j0][1]));
            pA[kk][1] = rnd2h(exp2f(s[j0][2]), exp2f(s[j0][3]));
            pA[kk][2] = rnd2h(exp2f(s[j1][0]), exp2f(s[j1][1]));
            pA[kk][3] = rnd2h(exp2f(s[j1][2]), exp2f(s[j1][3]));
            mma16816(osum, pA[kk], HONES, HONES);
        }

        // ---- O += P V (V fragments front-batched per kk) ----
        #pragma unroll
        for (int kk = 0; kk < 4; kk++) {
            uint32_t vf[4][4];
            #pragma unroll
            for (int jp = 0; jp < 4; jp++)
                ldsm4t(vf[jp], sV + ((vrow_b + kk*16) * ASTR + jp*16 + vcolb) * 2);
            #pragma unroll
            for (int jp = 0; jp < 4; jp++) {
                const int j2 = 2*jp;
                mma16816(o[j2],   pA[kk], vf[jp][0], vf[jp][1]);
                mma16816(o[j2+1], pA[kk], vf[jp][2], vf[jp][3]);
            }
        }
        if (++ring == NKV) ring = 0;
    }

    // ---- normalize + write fp16 att ----
    const int b = bh / HEADS, h = bh % HEADS;
    const float inv0 = 1.0f / osum[0], inv1 = 1.0f / osum[2];
    const int n0 = qt*128 + w*16 + g;
    size_t base0 = ((size_t)(b*SEQ + n0))*CDIM + h*HDIM;
    size_t base1 = base0 + (size_t)8*CDIM;
    #pragma unroll
    for (int nj = 0; nj < 8; nj++) {
        int hd = nj*8 + t2;
        *(uint32_t*)&g_a[base0 + hd] = rnd2h(o[nj][0]*inv0, o[nj][1]*inv0);
        *(uint32_t*)&g_a[base1 + hd] = rnd2h(o[nj][2]*inv1, o[nj][3]*inv1);
    }
}

// ---------------------------------------------------------------------------
extern "C" void kernel_launch(void* const* d_in, const int* in_sizes, int n_in,
                              void* d_out, int out_size) {
    const float* x = nullptr; const float* w_qkv = nullptr;
    const float* w_proj = nullptr; const float* b_proj = nullptr;
    for (int i = 0; i < n_in; i++) {
        switch (in_sizes[i]) {
            case BATCH*SEQ*CDIM: x      = (const float*)d_in[i]; break;
            case 3*CDIM*CDIM:    w_qkv  = (const float*)d_in[i]; break;
            case CDIM*CDIM:      w_proj = (const float*)d_in[i]; break;
            case CDIM:           b_proj = (const float*)d_in[i]; break;
        }
    }
    float* out = (float*)d_out;

    const int gemm_smem = 3*(ATB + 128*GSTR*2);   // 110592 (2 CTAs/SM)
    const int attn_smem = AQT + NKV*ASTG;         // 92160  (2 CTAs/SM)

    static void *xp=nullptr,*wq,*wp;
    if (!xp) {
        cudaGetSymbolAddress(&xp, g_x);
        cudaGetSymbolAddress(&wq, g_wq); cudaGetSymbolAddress(&wp, g_wp);
        cudaFuncSetAttribute(qkv_tc_kernel,  cudaFuncAttributeMaxDynamicSharedMemorySize, gemm_smem);
        cudaFuncSetAttribute(proj_tc_kernel, cudaFuncAttributeMaxDynamicSharedMemorySize, gemm_smem);
        cudaFuncSetAttribute(attn_tc_kernel, cudaFuncAttributeMaxDynamicSharedMemorySize, attn_smem);
    }

    const int total4 = NX4 + NWQ4 + NWP4;
    round_all_kernel<<<(total4 + 255)/256, 256>>>(
        (const float4*)x, (const float4*)w_qkv, (const float4*)w_proj,
        (uint64_t*)xp, (uint64_t*)wq, (uint64_t*)wp);

    qkv_tc_kernel<<<dim3(18, 64), 256, gemm_smem>>>();
    attn_tc_kernel<<<dim3(8, 96), 256, attn_smem>>>();
    proj_tc_kernel<<<dim3(6, 64), 256, gemm_smem>>>(b_proj, out);
}